// round 13
// baseline (speedup 1.0000x reference)
#include <cuda_runtime.h>
#include <cuda_bf16.h>
#include <cstddef>
#include <cstdint>

// ---------------------------------------------------------------------------
// Problem dims (fixed)
// ---------------------------------------------------------------------------
#define L_SEQ   2048
#define NBATCH  4
#define DMODEL  1024
#define DINNER  2048
#define DSTATE  16
#define DTRANK  64
#define NROWS   (NBATCH * L_SEQ)          // 8192
#define DBC_W   (DTRANK + 2 * DSTATE)     // 96

// ---------------------------------------------------------------------------
// Scratch (static __device__ — no allocations allowed)
// ---------------------------------------------------------------------------
__device__ float g_xz[(size_t)NROWS * (2 * DINNER)];   // in-proj output (xc | z)
__device__ float g_xc[(size_t)NROWS * DINNER];         // conv+silu output
__device__ float g_dbc[(size_t)NROWS * DBC_W];         // x-proj output (dt | B | C)
__device__ float g_delta[(size_t)NROWS * DINNER];      // softplus(dt @ W_dt + b_dt)

// bf16 hi/lo split buffers (K-concat width 3K)
__device__ __nv_bfloat16 g_x2   [(size_t)NROWS  * (3 * DMODEL)];     // 8192 x 3072
__device__ __nv_bfloat16 g_win2 [(size_t)(2*DINNER) * (3 * DMODEL)]; // 4096 x 3072
__device__ __nv_bfloat16 g_dt2  [(size_t)NROWS  * (3 * DTRANK)];     // 8192 x 192
__device__ __nv_bfloat16 g_wdt2 [(size_t)DINNER * (3 * DTRANK)];     // 2048 x 192
__device__ __nv_bfloat16 g_y2   [(size_t)NROWS  * (3 * DINNER)];     // 8192 x 6144 (written by scan)
__device__ __nv_bfloat16 g_wout2[(size_t)DMODEL * (3 * DINNER)];     // 1024 x 6144

// ---------------------------------------------------------------------------
// Math helpers
// ---------------------------------------------------------------------------
typedef unsigned long long u64;

__device__ __forceinline__ u64 pk2(float a) {
    u64 r;
    asm("mov.b64 %0, {%1, %2};" : "=l"(r) : "f"(a), "f"(a));
    return r;
}
__device__ __forceinline__ void ffma2(u64 &d, u64 a, u64 b) {
    asm("fma.rn.f32x2 %0, %1, %2, %0;" : "+l"(d) : "l"(a), "l"(b));
}
__device__ __forceinline__ float2 up2(u64 v) {
    float2 f;
    asm("mov.b64 {%0, %1}, %2;" : "=f"(f.x), "=f"(f.y) : "l"(v));
    return f;
}
__device__ __forceinline__ float ex2f(float x) {
    float r;
    asm("ex2.approx.ftz.f32 %0, %1;" : "=f"(r) : "f"(x));
    return r;
}
__device__ __forceinline__ float softplus_f(float x) {
    if (x > 20.f) return x;
    return log1pf(__expf(x));
}
__device__ __forceinline__ float sigmoid_f(float x) {
    return 1.f / (1.f + __expf(-x));
}
__device__ __forceinline__ uint32_t smem_u32(const void* p) {
    uint32_t addr;
    asm("{ .reg .u64 tmp; cvta.to.shared.u64 tmp, %1; cvt.u32.u64 %0, tmp; }"
        : "=r"(addr) : "l"(p));
    return addr;
}
__device__ __forceinline__ void cp_async16(void* s, const void* g) {
    uint32_t sa = smem_u32(s);
    asm volatile("cp.async.cg.shared.global [%0], [%1], 16;" :: "r"(sa), "l"(g) : "memory");
}
#define CP_COMMIT() asm volatile("cp.async.commit_group;" ::: "memory")
#define CP_WAIT1()  asm volatile("cp.async.wait_group 1;" ::: "memory")

#define LDM_X4(r0, r1, r2, r3, addr) \
    asm volatile("ldmatrix.sync.aligned.m8n8.x4.shared.b16 {%0,%1,%2,%3}, [%4];" \
        : "=r"(r0), "=r"(r1), "=r"(r2), "=r"(r3) : "r"(addr))

#define MMA16816(c, a, b) \
    asm volatile("mma.sync.aligned.m16n8k16.row.col.f32.bf16.bf16.f32 " \
        "{%0,%1,%2,%3}, {%4,%5,%6,%7}, {%8,%9}, {%0,%1,%2,%3};" \
        : "+f"((c)[0]), "+f"((c)[1]), "+f"((c)[2]), "+f"((c)[3]) \
        : "r"((a)[0]), "r"((a)[1]), "r"((a)[2]), "r"((a)[3]), \
          "r"((b)[0]), "r"((b)[1]))

// ---------------------------------------------------------------------------
// bf16 hi/lo split conversion.  dst width = 3K.
//   ALAY=1 (A side): [hi | lo | hi]      ALAY=0 (B side): [hi | hi | lo]
// ---------------------------------------------------------------------------
__global__ void split_bf16_kernel(const float* __restrict__ src,
                                  __nv_bfloat16* __restrict__ dst,
                                  int R, int K, int ld, int alay)
{
    int K4 = K >> 2;
    int idx = blockIdx.x * blockDim.x + threadIdx.x;
    if (idx >= R * K4) return;
    int r  = idx / K4;
    int k4 = (idx - r * K4) << 2;
    float4 v = *(const float4*)(src + (size_t)r * ld + k4);
    float vv[4] = {v.x, v.y, v.z, v.w};
    unsigned hu[4], lu[4];
#pragma unroll
    for (int i = 0; i < 4; i++) {
        __nv_bfloat16 h = __float2bfloat16(vv[i]);
        __nv_bfloat16 l = __float2bfloat16(vv[i] - __bfloat162float(h));
        hu[i] = (unsigned)__bfloat16_as_ushort(h);
        lu[i] = (unsigned)__bfloat16_as_ushort(l);
    }
    uint2 H, L;
    H.x = hu[0] | (hu[1] << 16); H.y = hu[2] | (hu[3] << 16);
    L.x = lu[0] | (lu[1] << 16); L.y = lu[2] | (lu[3] << 16);
    __nv_bfloat16* row = dst + (size_t)r * (3 * K);
    *(uint2*)(row + k4)         = H;
    *(uint2*)(row + K + k4)     = alay ? L : H;
    *(uint2*)(row + 2 * K + k4) = alay ? H : L;
}

// ---------------------------------------------------------------------------
// HMMA (mma.sync bf16) NT GEMM: C[M,N] = A2[M,Keff] * B2[N,Keff]^T, fp32 acc.
// CTA tile 128x128, BK=32, 8 warps (4M x 2N), warp tile 32x64.
// cp.async 2-stage double-buffered; ldmatrix.x4 operand loads; rows padded to
// 40 bf16 (80B stride) for conflict-free ldmatrix.
// EPI==1: C = softplus(C + bias).  (R6-proven structure, verbatim.)
// ---------------------------------------------------------------------------
template <int EPI>
__global__ __launch_bounds__(256) void hmma_gemm(
    int Keff,
    const __nv_bfloat16* __restrict__ A2,
    const __nv_bfloat16* __restrict__ B2,
    float* __restrict__ C, int ldc,
    const float* __restrict__ bias)
{
    constexpr int LDS = 40;                      // bf16 elems per smem row
    __shared__ __nv_bfloat16 sA[2][128 * LDS];
    __shared__ __nv_bfloat16 sB[2][128 * LDS];

    const int tid = threadIdx.x;
    const int wid = tid >> 5;
    const int lid = tid & 31;
    const int row0 = blockIdx.y * 128;
    const int col0 = blockIdx.x * 128;
    const int wrow = (wid & 3) * 32;             // 4 warps along M
    const int wcol = (wid >> 2) * 64;            // 2 warps along N

    float acc[2][8][4];
#pragma unroll
    for (int i = 0; i < 2; i++)
#pragma unroll
        for (int j = 0; j < 8; j++)
#pragma unroll
            for (int q = 0; q < 4; q++) acc[i][j][q] = 0.f;

    const int nch = Keff >> 5;

    auto load_stage = [&](int st, int c) {
        const __nv_bfloat16* Ag = A2 + (size_t)row0 * Keff + (c << 5);
        const __nv_bfloat16* Bg = B2 + (size_t)col0 * Keff + (c << 5);
#pragma unroll
        for (int i = 0; i < 2; i++) {
            int idx = (i << 8) + tid;            // 0..511
            int r = idx >> 2, ch = idx & 3;      // 128 rows x 4 chunks(16B)
            cp_async16(&sA[st][r * LDS + ch * 8], Ag + (size_t)r * Keff + ch * 8);
        }
#pragma unroll
        for (int i = 0; i < 2; i++) {
            int idx = (i << 8) + tid;
            int r = idx >> 2, ch = idx & 3;
            cp_async16(&sB[st][r * LDS + ch * 8], Bg + (size_t)r * Keff + ch * 8);
        }
    };

    load_stage(0, 0);
    CP_COMMIT();

    for (int c = 0; c < nch; c++) {
        if (c + 1 < nch) load_stage((c + 1) & 1, c + 1);
        CP_COMMIT();
        CP_WAIT1();
        __syncthreads();

        const int st = c & 1;
        const uint32_t a_base = smem_u32(&sA[st][0]);
        const uint32_t b_base = smem_u32(&sB[st][0]);

#pragma unroll
        for (int ks = 0; ks < 2; ks++) {
            const int kk = ks * 16;
            uint32_t a[2][4];
#pragma unroll
            for (int mi = 0; mi < 2; mi++) {
                int row = wrow + mi * 16 + (lid & 15);
                uint32_t addr = a_base + (uint32_t)(row * LDS + kk + ((lid >> 4) << 3)) * 2;
                LDM_X4(a[mi][0], a[mi][1], a[mi][2], a[mi][3], addr);
            }
            uint32_t b[8][2];
#pragma unroll
            for (int j = 0; j < 4; j++) {
                int n = wcol + j * 16 + ((lid >> 4) << 3) + (lid & 7);
                int k = kk + (((lid >> 3) & 1) << 3);
                uint32_t addr = b_base + (uint32_t)(n * LDS + k) * 2;
                uint32_t r0, r1, r2, r3;
                LDM_X4(r0, r1, r2, r3, addr);
                b[2 * j][0] = r0;     b[2 * j][1] = r1;
                b[2 * j + 1][0] = r2; b[2 * j + 1][1] = r3;
            }
#pragma unroll
            for (int mi = 0; mi < 2; mi++)
#pragma unroll
                for (int nt = 0; nt < 8; nt++)
                    MMA16816(acc[mi][nt], a[mi], b[nt]);
        }
        __syncthreads();
    }

    // epilogue: lane (g=lid>>2, p=lid&3) holds rows g,g+8 and cols 2p,2p+1
    const int lrow = lid >> 2;
    const int lc   = (lid & 3) * 2;
#pragma unroll
    for (int mi = 0; mi < 2; mi++) {
#pragma unroll
        for (int nt = 0; nt < 8; nt++) {
            int r  = row0 + wrow + mi * 16 + lrow;
            int cb = col0 + wcol + nt * 8 + lc;
            float2 v0 = make_float2(acc[mi][nt][0], acc[mi][nt][1]);
            float2 v1 = make_float2(acc[mi][nt][2], acc[mi][nt][3]);
            if (EPI == 1) {
                v0.x = softplus_f(v0.x + bias[cb]);
                v0.y = softplus_f(v0.y + bias[cb + 1]);
                v1.x = softplus_f(v1.x + bias[cb]);
                v1.y = softplus_f(v1.y + bias[cb + 1]);
            }
            *(float2*)&C[(size_t)r * ldc + cb]       = v0;
            *(float2*)&C[(size_t)(r + 8) * ldc + cb] = v1;
        }
    }
}

// ---------------------------------------------------------------------------
// fp32 SIMT NT SGEMM (kept only for x-proj, N=96)
// ---------------------------------------------------------------------------
template <int BM, int BN, int BK, int TM, int TN, int NT>
__global__ __launch_bounds__(NT) void sgemm_nt(
    int M, int N, int K, int lda, int ldb, int ldc,
    const float* __restrict__ A, const float* __restrict__ B,
    float* __restrict__ C)
{
    __shared__ __align__(16) float As[BK][BM + 4];
    __shared__ __align__(16) float Bs[BK][BN + 4];

    const int tid = threadIdx.x;
    const int tx  = tid % (BN / TN);
    const int ty  = tid / (BN / TN);
    const int row0 = blockIdx.y * BM;
    const int col0 = blockIdx.x * BN;
    const int tm0 = ty * TM;
    const int tn0 = tx * TN;

    u64 acc[TM][TN / 2];
#pragma unroll
    for (int i = 0; i < TM; i++)
#pragma unroll
        for (int j = 0; j < TN / 2; j++) acc[i][j] = 0ull;

    for (int k0 = 0; k0 < K; k0 += BK) {
#pragma unroll
        for (int i = tid; i < BM * (BK / 4); i += NT) {
            int r = i / (BK / 4);
            int c = (i % (BK / 4)) * 4;
            float4 v = *(const float4*)&A[(size_t)(row0 + r) * lda + k0 + c];
            As[c + 0][r] = v.x; As[c + 1][r] = v.y;
            As[c + 2][r] = v.z; As[c + 3][r] = v.w;
        }
#pragma unroll
        for (int i = tid; i < BN * (BK / 4); i += NT) {
            int r = i / (BK / 4);
            int c = (i % (BK / 4)) * 4;
            float4 v = *(const float4*)&B[(size_t)(col0 + r) * ldb + k0 + c];
            Bs[c + 0][r] = v.x; Bs[c + 1][r] = v.y;
            Bs[c + 2][r] = v.z; Bs[c + 3][r] = v.w;
        }
        __syncthreads();

#pragma unroll
        for (int k = 0; k < BK; k++) {
            u64 bp[TN / 2];
            const u64* brow = reinterpret_cast<const u64*>(&Bs[k][tn0]);
#pragma unroll
            for (int j = 0; j < TN / 2; j++) bp[j] = brow[j];
#pragma unroll
            for (int i = 0; i < TM; i++) {
                u64 ap = pk2(As[k][tm0 + i]);
#pragma unroll
                for (int j = 0; j < TN / 2; j++) ffma2(acc[i][j], ap, bp[j]);
            }
        }
        __syncthreads();
    }

#pragma unroll
    for (int i = 0; i < TM; i++) {
        int r = row0 + tm0 + i;
#pragma unroll
        for (int j = 0; j < TN / 2; j++) {
            int c = col0 + tn0 + 2 * j;
            float2 v = up2(acc[i][j]);
            *reinterpret_cast<float2*>(&C[(size_t)r * ldc + c]) = v;
        }
    }
}

// ---------------------------------------------------------------------------
// Causal depthwise conv (k=4, left pad 3) + SiLU.  4 timesteps per thread.
// ---------------------------------------------------------------------------
__global__ void conv_silu_kernel(const float* __restrict__ xz,
                                 const float* __restrict__ w,
                                 const float* __restrict__ bias,
                                 float* __restrict__ out)
{
    int idx = blockIdx.x * blockDim.x + threadIdx.x;
    if (idx >= (NROWS / 4) * DINNER) return;
    int d  = idx % DINNER;
    int g  = idx / DINNER;
    int tg = g % (L_SEQ / 4);
    int b  = g / (L_SEQ / 4);
    int t0 = tg * 4;

    const float* base = xz + (size_t)(b * L_SEQ) * (2 * DINNER) + d;
    float v[7];
#pragma unroll
    for (int j = 0; j < 7; j++) {
        int tt = t0 - 3 + j;
        v[j] = (tt >= 0) ? base[(size_t)tt * (2 * DINNER)] : 0.f;
    }
    float4 wv = *(const float4*)(w + d * 4);
    float bs = bias[d];
    float* ob = out + (size_t)(b * L_SEQ + t0) * DINNER + d;
#pragma unroll
    for (int i = 0; i < 4; i++) {
        float a = bs;
        a = fmaf(wv.x, v[i],     a);
        a = fmaf(wv.y, v[i + 1], a);
        a = fmaf(wv.z, v[i + 2], a);
        a = fmaf(wv.w, v[i + 3], a);
        ob[(size_t)i * DINNER] = a * sigmoid_f(a);
    }
}

// ---------------------------------------------------------------------------
// Selective scan.  Writes the out-proj A-operand split [hi|lo|hi] directly.
// ---------------------------------------------------------------------------
#define SCAN_T 64
__global__ __launch_bounds__(SCAN_T) void scan_kernel(
    const float* __restrict__ xc, const float* __restrict__ delta,
    const float* __restrict__ dbc, const float* __restrict__ xz,
    const float* __restrict__ A_raw, const float* __restrict__ Dv,
    __nv_bfloat16* __restrict__ y2)
{
    const int tid = threadIdx.x;
    const int d   = blockIdx.x * SCAN_T + tid;
    const int b   = blockIdx.y;
    const int base = b * L_SEQ;

    __shared__ __align__(16) float bc[2][32];

    float h[DSTATE], a2[DSTATE];
    const float LOG2E = 1.4426950408889634f;
#pragma unroll
    for (int n = 0; n < DSTATE; n++) {
        h[n]  = 0.f;
        a2[n] = -expf(A_raw[n * DINNER + d]) * LOG2E;
    }
    const float Dd = Dv[d];

    constexpr int PB = 8;
    float vring[PB];
    if (tid < 32) {
        bc[0][tid] = dbc[(size_t)base * DBC_W + DTRANK + tid];          // time 0
#pragma unroll
        for (int j = 0; j < PB; j++)
            vring[j] = dbc[(size_t)(base + 1 + j) * DBC_W + DTRANK + tid];
    }

    constexpr int PV = 8;
    float dltb[PV], xvb[PV], zvb[PV];
#pragma unroll
    for (int j = 0; j < PV; j++) {
        size_t r = (size_t)(base + j);
        dltb[j] = delta[r * DINNER + d];
        xvb[j]  = xc[r * DINNER + d];
        zvb[j]  = xz[r * (2 * DINNER) + DINNER + d];
    }
    __syncthreads();

    for (int t = 0; t < L_SEQ; t++) {
        const int s = t % PV;
        const float dlt = dltb[s];
        const float xv  = xvb[s];
        const float zv  = zvb[s];
        if (t + PV < L_SEQ) {
            size_t r = (size_t)(base + t + PV);
            dltb[s] = delta[r * DINNER + d];
            xvb[s]  = xc[r * DINNER + d];
            zvb[s]  = xz[r * (2 * DINNER) + DINNER + d];
        }
        if (tid < 32) {
            if (t + 1 < L_SEQ) bc[(t + 1) & 1][tid] = vring[t % PB];
            if (t + 1 + PB < L_SEQ)
                vring[t % PB] =
                    dbc[(size_t)(base + t + 1 + PB) * DBC_W + DTRANK + tid];
        }

        const float* cur = bc[t & 1];
        float Bv[DSTATE], Cv[DSTATE];
        *(float4*)&Bv[0]  = *(const float4*)&cur[0];
        *(float4*)&Bv[4]  = *(const float4*)&cur[4];
        *(float4*)&Bv[8]  = *(const float4*)&cur[8];
        *(float4*)&Bv[12] = *(const float4*)&cur[12];
        *(float4*)&Cv[0]  = *(const float4*)&cur[16];
        *(float4*)&Cv[4]  = *(const float4*)&cur[20];
        *(float4*)&Cv[8]  = *(const float4*)&cur[24];
        *(float4*)&Cv[12] = *(const float4*)&cur[28];

        const float dx = dlt * xv;
        float acc = Dd * xv;
#pragma unroll
        for (int n = 0; n < DSTATE; n++) {
            float da = ex2f(dlt * a2[n]);
            h[n] = fmaf(da, h[n], dx * Bv[n]);
            acc  = fmaf(Cv[n], h[n], acc);
        }
        float val = acc * (zv * sigmoid_f(zv));
        __nv_bfloat16 hh = __float2bfloat16(val);
        __nv_bfloat16 ll = __float2bfloat16(val - __bfloat162float(hh));
        __nv_bfloat16* row = y2 + (size_t)(base + t) * (3 * DINNER);
        row[d]              = hh;
        row[DINNER + d]     = ll;
        row[2 * DINNER + d] = hh;
        __syncthreads();
    }
}

// ---------------------------------------------------------------------------
// Launch
// ---------------------------------------------------------------------------
extern "C" void kernel_launch(void* const* d_in, const int* in_sizes, int n_in,
                              void* d_out, int out_size)
{
    const float* x      = (const float*)d_in[0];
    const float* W_in   = (const float*)d_in[1];
    const float* conv_w = (const float*)d_in[2];
    const float* conv_b = (const float*)d_in[3];
    const float* W_x    = (const float*)d_in[4];
    const float* W_dt   = (const float*)d_in[5];
    const float* b_dt   = (const float*)d_in[6];
    const float* A_raw  = (const float*)d_in[7];
    const float* Dv     = (const float*)d_in[8];
    const float* W_out  = (const float*)d_in[9];
    float* out = (float*)d_out;

    float *xz, *xc, *dbc, *delta;
    __nv_bfloat16 *x2, *win2, *dt2, *wdt2, *y2, *wout2;
    cudaGetSymbolAddress((void**)&xz,    g_xz);
    cudaGetSymbolAddress((void**)&xc,    g_xc);
    cudaGetSymbolAddress((void**)&dbc,   g_dbc);
    cudaGetSymbolAddress((void**)&delta, g_delta);
    cudaGetSymbolAddress((void**)&x2,    g_x2);
    cudaGetSymbolAddress((void**)&win2,  g_win2);
    cudaGetSymbolAddress((void**)&dt2,   g_dt2);
    cudaGetSymbolAddress((void**)&wdt2,  g_wdt2);
    cudaGetSymbolAddress((void**)&y2,    g_y2);
    cudaGetSymbolAddress((void**)&wout2, g_wout2);

    // --- in-proj:  xz[8192,4096] = x[8192,1024] @ W_in[4096,1024]^T ---
    {
        int nA = NROWS * (DMODEL / 4);
        split_bf16_kernel<<<(nA + 255) / 256, 256>>>(x, x2, NROWS, DMODEL, DMODEL, 1);
        int nB = (2 * DINNER) * (DMODEL / 4);
        split_bf16_kernel<<<(nB + 255) / 256, 256>>>(W_in, win2, 2 * DINNER, DMODEL, DMODEL, 0);
        dim3 grid((2 * DINNER) / 128, NROWS / 128);
        hmma_gemm<0><<<grid, 256>>>(3 * DMODEL, x2, win2, xz, 2 * DINNER, nullptr);
    }
    // --- causal depthwise conv + silu -> xc ---
    {
        int total = (NROWS / 4) * DINNER;
        conv_silu_kernel<<<(total + 255) / 256, 256>>>(xz, conv_w, conv_b, xc);
    }
    // --- x-proj (fp32 SIMT):  dbc[8192,96] = xc @ W_x[96,2048]^T ---
    {
        dim3 grid(1, NROWS / 32);
        sgemm_nt<32, 96, 16, 2, 8, 192><<<grid, 192>>>(
            NROWS, DBC_W, DINNER, DINNER, DINNER, DBC_W, xc, W_x, dbc);
    }
    // --- delta = softplus(dbc[:, :64] @ W_dt[2048,64]^T + b_dt) ---
    {
        int nA = NROWS * (DTRANK / 4);
        split_bf16_kernel<<<(nA + 255) / 256, 256>>>(dbc, dt2, NROWS, DTRANK, DBC_W, 1);
        int nB = DINNER * (DTRANK / 4);
        split_bf16_kernel<<<(nB + 255) / 256, 256>>>(W_dt, wdt2, DINNER, DTRANK, DTRANK, 0);
        dim3 grid(DINNER / 128, NROWS / 128);
        hmma_gemm<1><<<grid, 256>>>(3 * DTRANK, dt2, wdt2, delta, DINNER, b_dt);
    }
    // --- selective scan (+ D skip + silu(z) gate) -> y2 split directly ---
    {
        dim3 grid(DINNER / SCAN_T, NBATCH);
        scan_kernel<<<grid, SCAN_T>>>(xc, delta, dbc, xz, A_raw, Dv, y2);
    }
    // --- out-proj:  out[8192,1024] = y @ W_out[1024,2048]^T ---
    {
        int nB = DMODEL * (DINNER / 4);
        split_bf16_kernel<<<(nB + 255) / 256, 256>>>(W_out, wout2, DMODEL, DINNER, DINNER, 0);
        dim3 grid(DMODEL / 128, NROWS / 128);
        hmma_gemm<0><<<grid, 256>>>(3 * DINNER, y2, wout2, out, DMODEL, nullptr);
    }
}

// round 14
// speedup vs baseline: 1.1206x; 1.1206x over previous
#include <cuda_runtime.h>
#include <cuda_fp16.h>
#include <cstddef>
#include <cstdint>

// ---------------------------------------------------------------------------
// Problem dims (fixed)
// ---------------------------------------------------------------------------
#define L_SEQ   2048
#define NBATCH  4
#define DMODEL  1024
#define DINNER  2048
#define DSTATE  16
#define DTRANK  64
#define NROWS   (NBATCH * L_SEQ)          // 8192
#define DBC_W   (DTRANK + 2 * DSTATE)     // 96

// ---------------------------------------------------------------------------
// Scratch (static __device__ — no allocations allowed)
// ---------------------------------------------------------------------------
__device__ float g_xz[(size_t)NROWS * (2 * DINNER)];   // in-proj output (xc | z)
__device__ float g_xc[(size_t)NROWS * DINNER];         // conv+silu output
__device__ float g_dbc[(size_t)NROWS * DBC_W];         // x-proj output (dt | B | C)
__device__ float g_delta[(size_t)NROWS * DINNER];      // softplus(dt @ W_dt + b_dt)

// fp16 hi/lo split buffers (K-concat width 2K)
__device__ __half g_x2   [(size_t)NROWS  * (2 * DMODEL)];     // 8192 x 2048
__device__ __half g_win2 [(size_t)(2*DINNER) * (2 * DMODEL)]; // 4096 x 2048
__device__ __half g_dt2  [(size_t)NROWS  * (2 * DTRANK)];     // 8192 x 128
__device__ __half g_wdt2 [(size_t)DINNER * (2 * DTRANK)];     // 2048 x 128
__device__ __half g_y2   [(size_t)NROWS  * (2 * DINNER)];     // 8192 x 4096 (written by scan)
__device__ __half g_wout2[(size_t)DMODEL * (2 * DINNER)];     // 1024 x 4096

// ---------------------------------------------------------------------------
// Math helpers
// ---------------------------------------------------------------------------
typedef unsigned long long u64;

__device__ __forceinline__ u64 pk2(float a) {
    u64 r;
    asm("mov.b64 %0, {%1, %2};" : "=l"(r) : "f"(a), "f"(a));
    return r;
}
__device__ __forceinline__ void ffma2(u64 &d, u64 a, u64 b) {
    asm("fma.rn.f32x2 %0, %1, %2, %0;" : "+l"(d) : "l"(a), "l"(b));
}
__device__ __forceinline__ float2 up2(u64 v) {
    float2 f;
    asm("mov.b64 {%0, %1}, %2;" : "=f"(f.x), "=f"(f.y) : "l"(v));
    return f;
}
__device__ __forceinline__ float ex2f(float x) {
    float r;
    asm("ex2.approx.ftz.f32 %0, %1;" : "=f"(r) : "f"(x));
    return r;
}
__device__ __forceinline__ float softplus_f(float x) {
    if (x > 20.f) return x;
    return log1pf(__expf(x));
}
__device__ __forceinline__ float sigmoid_f(float x) {
    return 1.f / (1.f + __expf(-x));
}
__device__ __forceinline__ uint32_t smem_u32(const void* p) {
    uint32_t addr;
    asm("{ .reg .u64 tmp; cvta.to.shared.u64 tmp, %1; cvt.u32.u64 %0, tmp; }"
        : "=r"(addr) : "l"(p));
    return addr;
}
__device__ __forceinline__ void cp_async16(void* s, const void* g) {
    uint32_t sa = smem_u32(s);
    asm volatile("cp.async.cg.shared.global [%0], [%1], 16;" :: "r"(sa), "l"(g) : "memory");
}
#define CP_COMMIT() asm volatile("cp.async.commit_group;" ::: "memory")
#define CP_WAIT1()  asm volatile("cp.async.wait_group 1;" ::: "memory")

#define LDM_X4(r0, r1, r2, r3, addr) \
    asm volatile("ldmatrix.sync.aligned.m8n8.x4.shared.b16 {%0,%1,%2,%3}, [%4];" \
        : "=r"(r0), "=r"(r1), "=r"(r2), "=r"(r3) : "r"(addr))

#define MMA16816(c, a, b) \
    asm volatile("mma.sync.aligned.m16n8k16.row.col.f32.f16.f16.f32 " \
        "{%0,%1,%2,%3}, {%4,%5,%6,%7}, {%8,%9}, {%0,%1,%2,%3};" \
        : "+f"((c)[0]), "+f"((c)[1]), "+f"((c)[2]), "+f"((c)[3]) \
        : "r"((a)[0]), "r"((a)[1]), "r"((a)[2]), "r"((a)[3]), \
          "r"((b)[0]), "r"((b)[1]))

// ---------------------------------------------------------------------------
// fp16 hi/lo split conversion.  dst width = 2K.
//   ALAY=1 (A side): [hi | lo]      ALAY=0 (B side): [hi | hi]
// A reconstructs exactly (hi+lo, residual 2^-22); B carries fp16 quantization
// (2^-11), the only dropped term of the 2-term product.
// ---------------------------------------------------------------------------
__global__ void split_fp16_kernel(const float* __restrict__ src,
                                  __half* __restrict__ dst,
                                  int R, int K, int ld, int alay)
{
    int K4 = K >> 2;
    int idx = blockIdx.x * blockDim.x + threadIdx.x;
    if (idx >= R * K4) return;
    int r  = idx / K4;
    int k4 = (idx - r * K4) << 2;
    float4 v = *(const float4*)(src + (size_t)r * ld + k4);
    float vv[4] = {v.x, v.y, v.z, v.w};
    unsigned hu[4], lu[4];
#pragma unroll
    for (int i = 0; i < 4; i++) {
        __half h = __float2half(vv[i]);
        __half l = __float2half(vv[i] - __half2float(h));
        hu[i] = (unsigned)__half_as_ushort(h);
        lu[i] = (unsigned)__half_as_ushort(l);
    }
    uint2 H, L;
    H.x = hu[0] | (hu[1] << 16); H.y = hu[2] | (hu[3] << 16);
    L.x = lu[0] | (lu[1] << 16); L.y = lu[2] | (lu[3] << 16);
    __half* row = dst + (size_t)r * (2 * K);
    *(uint2*)(row + k4)     = H;
    *(uint2*)(row + K + k4) = alay ? L : H;
}

// ---------------------------------------------------------------------------
// HMMA (mma.sync fp16) NT GEMM: C[M,N] = A2[M,Keff] * B2[N,Keff]^T, fp32 acc.
// CTA tile 128x128, BK=32, 8 warps (4M x 2N), warp tile 32x64.
// cp.async 2-stage double-buffered; ldmatrix.x4 operand loads; rows padded to
// 40 halfs (80B stride) for conflict-free ldmatrix.
// EPI==1: C = softplus(C + bias).  (R6/R12-proven structure; f16 opcode.)
// ---------------------------------------------------------------------------
template <int EPI>
__global__ __launch_bounds__(256) void hmma_gemm(
    int Keff,
    const __half* __restrict__ A2,
    const __half* __restrict__ B2,
    float* __restrict__ C, int ldc,
    const float* __restrict__ bias)
{
    constexpr int LDS = 40;                      // halfs per smem row
    __shared__ __half sA[2][128 * LDS];
    __shared__ __half sB[2][128 * LDS];

    const int tid = threadIdx.x;
    const int wid = tid >> 5;
    const int lid = tid & 31;
    const int row0 = blockIdx.y * 128;
    const int col0 = blockIdx.x * 128;
    const int wrow = (wid & 3) * 32;             // 4 warps along M
    const int wcol = (wid >> 2) * 64;            // 2 warps along N

    float acc[2][8][4];
#pragma unroll
    for (int i = 0; i < 2; i++)
#pragma unroll
        for (int j = 0; j < 8; j++)
#pragma unroll
            for (int q = 0; q < 4; q++) acc[i][j][q] = 0.f;

    const int nch = Keff >> 5;

    auto load_stage = [&](int st, int c) {
        const __half* Ag = A2 + (size_t)row0 * Keff + (c << 5);
        const __half* Bg = B2 + (size_t)col0 * Keff + (c << 5);
#pragma unroll
        for (int i = 0; i < 2; i++) {
            int idx = (i << 8) + tid;            // 0..511
            int r = idx >> 2, ch = idx & 3;      // 128 rows x 4 chunks(16B)
            cp_async16(&sA[st][r * LDS + ch * 8], Ag + (size_t)r * Keff + ch * 8);
        }
#pragma unroll
        for (int i = 0; i < 2; i++) {
            int idx = (i << 8) + tid;
            int r = idx >> 2, ch = idx & 3;
            cp_async16(&sB[st][r * LDS + ch * 8], Bg + (size_t)r * Keff + ch * 8);
        }
    };

    load_stage(0, 0);
    CP_COMMIT();

    for (int c = 0; c < nch; c++) {
        if (c + 1 < nch) load_stage((c + 1) & 1, c + 1);
        CP_COMMIT();
        CP_WAIT1();
        __syncthreads();

        const int st = c & 1;
        const uint32_t a_base = smem_u32(&sA[st][0]);
        const uint32_t b_base = smem_u32(&sB[st][0]);

#pragma unroll
        for (int ks = 0; ks < 2; ks++) {
            const int kk = ks * 16;
            uint32_t a[2][4];
#pragma unroll
            for (int mi = 0; mi < 2; mi++) {
                int row = wrow + mi * 16 + (lid & 15);
                uint32_t addr = a_base + (uint32_t)(row * LDS + kk + ((lid >> 4) << 3)) * 2;
                LDM_X4(a[mi][0], a[mi][1], a[mi][2], a[mi][3], addr);
            }
            uint32_t b[8][2];
#pragma unroll
            for (int j = 0; j < 4; j++) {
                int n = wcol + j * 16 + ((lid >> 4) << 3) + (lid & 7);
                int k = kk + (((lid >> 3) & 1) << 3);
                uint32_t addr = b_base + (uint32_t)(n * LDS + k) * 2;
                uint32_t r0, r1, r2, r3;
                LDM_X4(r0, r1, r2, r3, addr);
                b[2 * j][0] = r0;     b[2 * j][1] = r1;
                b[2 * j + 1][0] = r2; b[2 * j + 1][1] = r3;
            }
#pragma unroll
            for (int mi = 0; mi < 2; mi++)
#pragma unroll
                for (int nt = 0; nt < 8; nt++)
                    MMA16816(acc[mi][nt], a[mi], b[nt]);
        }
        __syncthreads();
    }

    // epilogue: lane (g=lid>>2, p=lid&3) holds rows g,g+8 and cols 2p,2p+1
    const int lrow = lid >> 2;
    const int lc   = (lid & 3) * 2;
#pragma unroll
    for (int mi = 0; mi < 2; mi++) {
#pragma unroll
        for (int nt = 0; nt < 8; nt++) {
            int r  = row0 + wrow + mi * 16 + lrow;
            int cb = col0 + wcol + nt * 8 + lc;
            float2 v0 = make_float2(acc[mi][nt][0], acc[mi][nt][1]);
            float2 v1 = make_float2(acc[mi][nt][2], acc[mi][nt][3]);
            if (EPI == 1) {
                v0.x = softplus_f(v0.x + bias[cb]);
                v0.y = softplus_f(v0.y + bias[cb + 1]);
                v1.x = softplus_f(v1.x + bias[cb]);
                v1.y = softplus_f(v1.y + bias[cb + 1]);
            }
            *(float2*)&C[(size_t)r * ldc + cb]       = v0;
            *(float2*)&C[(size_t)(r + 8) * ldc + cb] = v1;
        }
    }
}

// ---------------------------------------------------------------------------
// fp32 SIMT NT SGEMM (kept only for x-proj, N=96)
// ---------------------------------------------------------------------------
template <int BM, int BN, int BK, int TM, int TN, int NT>
__global__ __launch_bounds__(NT) void sgemm_nt(
    int M, int N, int K, int lda, int ldb, int ldc,
    const float* __restrict__ A, const float* __restrict__ B,
    float* __restrict__ C)
{
    __shared__ __align__(16) float As[BK][BM + 4];
    __shared__ __align__(16) float Bs[BK][BN + 4];

    const int tid = threadIdx.x;
    const int tx  = tid % (BN / TN);
    const int ty  = tid / (BN / TN);
    const int row0 = blockIdx.y * BM;
    const int col0 = blockIdx.x * BN;
    const int tm0 = ty * TM;
    const int tn0 = tx * TN;

    u64 acc[TM][TN / 2];
#pragma unroll
    for (int i = 0; i < TM; i++)
#pragma unroll
        for (int j = 0; j < TN / 2; j++) acc[i][j] = 0ull;

    for (int k0 = 0; k0 < K; k0 += BK) {
#pragma unroll
        for (int i = tid; i < BM * (BK / 4); i += NT) {
            int r = i / (BK / 4);
            int c = (i % (BK / 4)) * 4;
            float4 v = *(const float4*)&A[(size_t)(row0 + r) * lda + k0 + c];
            As[c + 0][r] = v.x; As[c + 1][r] = v.y;
            As[c + 2][r] = v.z; As[c + 3][r] = v.w;
        }
#pragma unroll
        for (int i = tid; i < BN * (BK / 4); i += NT) {
            int r = i / (BK / 4);
            int c = (i % (BK / 4)) * 4;
            float4 v = *(const float4*)&B[(size_t)(col0 + r) * ldb + k0 + c];
            Bs[c + 0][r] = v.x; Bs[c + 1][r] = v.y;
            Bs[c + 2][r] = v.z; Bs[c + 3][r] = v.w;
        }
        __syncthreads();

#pragma unroll
        for (int k = 0; k < BK; k++) {
            u64 bp[TN / 2];
            const u64* brow = reinterpret_cast<const u64*>(&Bs[k][tn0]);
#pragma unroll
            for (int j = 0; j < TN / 2; j++) bp[j] = brow[j];
#pragma unroll
            for (int i = 0; i < TM; i++) {
                u64 ap = pk2(As[k][tm0 + i]);
#pragma unroll
                for (int j = 0; j < TN / 2; j++) ffma2(acc[i][j], ap, bp[j]);
            }
        }
        __syncthreads();
    }

#pragma unroll
    for (int i = 0; i < TM; i++) {
        int r = row0 + tm0 + i;
#pragma unroll
        for (int j = 0; j < TN / 2; j++) {
            int c = col0 + tn0 + 2 * j;
            float2 v = up2(acc[i][j]);
            *reinterpret_cast<float2*>(&C[(size_t)r * ldc + c]) = v;
        }
    }
}

// ---------------------------------------------------------------------------
// Causal depthwise conv (k=4, left pad 3) + SiLU.  4 timesteps per thread.
// ---------------------------------------------------------------------------
__global__ void conv_silu_kernel(const float* __restrict__ xz,
                                 const float* __restrict__ w,
                                 const float* __restrict__ bias,
                                 float* __restrict__ out)
{
    int idx = blockIdx.x * blockDim.x + threadIdx.x;
    if (idx >= (NROWS / 4) * DINNER) return;
    int d  = idx % DINNER;
    int g  = idx / DINNER;
    int tg = g % (L_SEQ / 4);
    int b  = g / (L_SEQ / 4);
    int t0 = tg * 4;

    const float* base = xz + (size_t)(b * L_SEQ) * (2 * DINNER) + d;
    float v[7];
#pragma unroll
    for (int j = 0; j < 7; j++) {
        int tt = t0 - 3 + j;
        v[j] = (tt >= 0) ? base[(size_t)tt * (2 * DINNER)] : 0.f;
    }
    float4 wv = *(const float4*)(w + d * 4);
    float bs = bias[d];
    float* ob = out + (size_t)(b * L_SEQ + t0) * DINNER + d;
#pragma unroll
    for (int i = 0; i < 4; i++) {
        float a = bs;
        a = fmaf(wv.x, v[i],     a);
        a = fmaf(wv.y, v[i + 1], a);
        a = fmaf(wv.z, v[i + 2], a);
        a = fmaf(wv.w, v[i + 3], a);
        ob[(size_t)i * DINNER] = a * sigmoid_f(a);
    }
}

// ---------------------------------------------------------------------------
// Selective scan.  Writes the out-proj A-operand fp16 split [hi|lo] directly.
// ---------------------------------------------------------------------------
#define SCAN_T 64
__global__ __launch_bounds__(SCAN_T) void scan_kernel(
    const float* __restrict__ xc, const float* __restrict__ delta,
    const float* __restrict__ dbc, const float* __restrict__ xz,
    const float* __restrict__ A_raw, const float* __restrict__ Dv,
    __half* __restrict__ y2)
{
    const int tid = threadIdx.x;
    const int d   = blockIdx.x * SCAN_T + tid;
    const int b   = blockIdx.y;
    const int base = b * L_SEQ;

    __shared__ __align__(16) float bc[2][32];

    float h[DSTATE], a2[DSTATE];
    const float LOG2E = 1.4426950408889634f;
#pragma unroll
    for (int n = 0; n < DSTATE; n++) {
        h[n]  = 0.f;
        a2[n] = -expf(A_raw[n * DINNER + d]) * LOG2E;
    }
    const float Dd = Dv[d];

    constexpr int PB = 8;
    float vring[PB];
    if (tid < 32) {
        bc[0][tid] = dbc[(size_t)base * DBC_W + DTRANK + tid];          // time 0
#pragma unroll
        for (int j = 0; j < PB; j++)
            vring[j] = dbc[(size_t)(base + 1 + j) * DBC_W + DTRANK + tid];
    }

    constexpr int PV = 8;
    float dltb[PV], xvb[PV], zvb[PV];
#pragma unroll
    for (int j = 0; j < PV; j++) {
        size_t r = (size_t)(base + j);
        dltb[j] = delta[r * DINNER + d];
        xvb[j]  = xc[r * DINNER + d];
        zvb[j]  = xz[r * (2 * DINNER) + DINNER + d];
    }
    __syncthreads();

    for (int t = 0; t < L_SEQ; t++) {
        const int s = t % PV;
        const float dlt = dltb[s];
        const float xv  = xvb[s];
        const float zv  = zvb[s];
        if (t + PV < L_SEQ) {
            size_t r = (size_t)(base + t + PV);
            dltb[s] = delta[r * DINNER + d];
            xvb[s]  = xc[r * DINNER + d];
            zvb[s]  = xz[r * (2 * DINNER) + DINNER + d];
        }
        if (tid < 32) {
            if (t + 1 < L_SEQ) bc[(t + 1) & 1][tid] = vring[t % PB];
            if (t + 1 + PB < L_SEQ)
                vring[t % PB] =
                    dbc[(size_t)(base + t + 1 + PB) * DBC_W + DTRANK + tid];
        }

        const float* cur = bc[t & 1];
        float Bv[DSTATE], Cv[DSTATE];
        *(float4*)&Bv[0]  = *(const float4*)&cur[0];
        *(float4*)&Bv[4]  = *(const float4*)&cur[4];
        *(float4*)&Bv[8]  = *(const float4*)&cur[8];
        *(float4*)&Bv[12] = *(const float4*)&cur[12];
        *(float4*)&Cv[0]  = *(const float4*)&cur[16];
        *(float4*)&Cv[4]  = *(const float4*)&cur[20];
        *(float4*)&Cv[8]  = *(const float4*)&cur[24];
        *(float4*)&Cv[12] = *(const float4*)&cur[28];

        const float dx = dlt * xv;
        float acc = Dd * xv;
#pragma unroll
        for (int n = 0; n < DSTATE; n++) {
            float da = ex2f(dlt * a2[n]);
            h[n] = fmaf(da, h[n], dx * Bv[n]);
            acc  = fmaf(Cv[n], h[n], acc);
        }
        float val = acc * (zv * sigmoid_f(zv));
        __half hh = __float2half(val);
        __half ll = __float2half(val - __half2float(hh));
        __half* row = y2 + (size_t)(base + t) * (2 * DINNER);
        row[d]          = hh;
        row[DINNER + d] = ll;
        __syncthreads();
    }
}

// ---------------------------------------------------------------------------
// Launch
// ---------------------------------------------------------------------------
extern "C" void kernel_launch(void* const* d_in, const int* in_sizes, int n_in,
                              void* d_out, int out_size)
{
    const float* x      = (const float*)d_in[0];
    const float* W_in   = (const float*)d_in[1];
    const float* conv_w = (const float*)d_in[2];
    const float* conv_b = (const float*)d_in[3];
    const float* W_x    = (const float*)d_in[4];
    const float* W_dt   = (const float*)d_in[5];
    const float* b_dt   = (const float*)d_in[6];
    const float* A_raw  = (const float*)d_in[7];
    const float* Dv     = (const float*)d_in[8];
    const float* W_out  = (const float*)d_in[9];
    float* out = (float*)d_out;

    float *xz, *xc, *dbc, *delta;
    __half *x2, *win2, *dt2, *wdt2, *y2, *wout2;
    cudaGetSymbolAddress((void**)&xz,    g_xz);
    cudaGetSymbolAddress((void**)&xc,    g_xc);
    cudaGetSymbolAddress((void**)&dbc,   g_dbc);
    cudaGetSymbolAddress((void**)&delta, g_delta);
    cudaGetSymbolAddress((void**)&x2,    g_x2);
    cudaGetSymbolAddress((void**)&win2,  g_win2);
    cudaGetSymbolAddress((void**)&dt2,   g_dt2);
    cudaGetSymbolAddress((void**)&wdt2,  g_wdt2);
    cudaGetSymbolAddress((void**)&y2,    g_y2);
    cudaGetSymbolAddress((void**)&wout2, g_wout2);

    // --- in-proj:  xz[8192,4096] = x[8192,1024] @ W_in[4096,1024]^T ---
    {
        int nA = NROWS * (DMODEL / 4);
        split_fp16_kernel<<<(nA + 255) / 256, 256>>>(x, x2, NROWS, DMODEL, DMODEL, 1);
        int nB = (2 * DINNER) * (DMODEL / 4);
        split_fp16_kernel<<<(nB + 255) / 256, 256>>>(W_in, win2, 2 * DINNER, DMODEL, DMODEL, 0);
        dim3 grid((2 * DINNER) / 128, NROWS / 128);
        hmma_gemm<0><<<grid, 256>>>(2 * DMODEL, x2, win2, xz, 2 * DINNER, nullptr);
    }
    // --- causal depthwise conv + silu -> xc ---
    {
        int total = (NROWS / 4) * DINNER;
        conv_silu_kernel<<<(total + 255) / 256, 256>>>(xz, conv_w, conv_b, xc);
    }
    // --- x-proj (fp32 SIMT):  dbc[8192,96] = xc @ W_x[96,2048]^T ---
    {
        dim3 grid(1, NROWS / 32);
        sgemm_nt<32, 96, 16, 2, 8, 192><<<grid, 192>>>(
            NROWS, DBC_W, DINNER, DINNER, DINNER, DBC_W, xc, W_x, dbc);
    }
    // --- delta = softplus(dbc[:, :64] @ W_dt[2048,64]^T + b_dt) ---
    {
        int nA = NROWS * (DTRANK / 4);
        split_fp16_kernel<<<(nA + 255) / 256, 256>>>(dbc, dt2, NROWS, DTRANK, DBC_W, 1);
        int nB = DINNER * (DTRANK / 4);
        split_fp16_kernel<<<(nB + 255) / 256, 256>>>(W_dt, wdt2, DINNER, DTRANK, DTRANK, 0);
        dim3 grid(DINNER / 128, NROWS / 128);
        hmma_gemm<1><<<grid, 256>>>(2 * DTRANK, dt2, wdt2, delta, DINNER, b_dt);
    }
    // --- selective scan (+ D skip + silu(z) gate) -> y2 fp16 split directly ---
    {
        dim3 grid(DINNER / SCAN_T, NBATCH);
        scan_kernel<<<grid, SCAN_T>>>(xc, delta, dbc, xz, A_raw, Dv, y2);
    }
    // --- out-proj:  out[8192,1024] = y @ W_out[1024,2048]^T ---
    {
        int nB = DMODEL * (DINNER / 4);
        split_fp16_kernel<<<(nB + 255) / 256, 256>>>(W_out, wout2, DMODEL, DINNER, DINNER, 0);
        dim3 grid(DMODEL / 128, NROWS / 128);
        hmma_gemm<0><<<grid, 256>>>(2 * DINNER, y2, wout2, out, DMODEL, nullptr);
    }
}